// round 2
// baseline (speedup 1.0000x reference)
#include <cuda_runtime.h>

// Ses2Seq: th <- th A^T + x B^T scanned 256 steps, then per-batch MLP eval.
// Reformulated via A = I + E binomial expansion truncated at J=24:
//   th_final[b] = sum_j d_j * (Etil^j theta) + sum_j c_{b,j} * (Etil^j B)
// with Etil = 100*(A - I), d_j = C(256,j)*0.01^j, c_{b,j} = 0.01^j * sum_k x[b,255-k] C(k,j).
// Only 24 streaming passes over A instead of 256.

#define NDIM   8838
#define NPAD   8960      // 70 * 128, float4-friendly padded width
#define NPAD4  2240      // NPAD / 4
#define JMAX   24
#define NV     25        // j = 0..24
#define NB     8
#define NT     256

__device__ float  g_E[(size_t)NDIM * NPAD];   // scaled E, padded columns (zeros)
__device__ float  g_K[NV][2][NPAD];           // Krylov vectors: [j][0]=Etil^j B, [j][1]=Etil^j theta
__device__ double g_c[NB][NV];
__device__ double g_d[NV];
__device__ float  g_th[NB][NDIM];

// ---------------------------------------------------------------------------
__global__ void build_E_kernel(const float* __restrict__ A) {
    size_t total  = (size_t)NDIM * NPAD;
    size_t stride = (size_t)gridDim.x * blockDim.x;
    for (size_t idx = (size_t)blockIdx.x * blockDim.x + threadIdx.x;
         idx < total; idx += stride) {
        int row = (int)(idx / NPAD);
        int col = (int)(idx - (size_t)row * NPAD);
        float v = 0.0f;
        if (col < NDIM) {
            v = A[(size_t)row * NDIM + col];
            if (col == row) v -= 1.0f;   // exact (Sterbenz, A_ii ~ 1)
            v *= 100.0f;
        }
        g_E[idx] = v;
    }
}

// ---------------------------------------------------------------------------
__global__ void init_K_kernel(const float* __restrict__ theta,
                              const float* __restrict__ Bv) {
    int i = blockIdx.x * blockDim.x + threadIdx.x;
    if (i < NPAD) {
        g_K[0][0][i] = (i < NDIM) ? Bv[i]    : 0.0f;
        g_K[0][1][i] = (i < NDIM) ? theta[i] : 0.0f;
    }
}

// ---------------------------------------------------------------------------
// One warp per row; both chains (B and theta) share the single stream of E.
__global__ void __launch_bounds__(256) krylov_kernel(int j) {
    int warp = threadIdx.x >> 5;
    int lane = threadIdx.x & 31;
    int row  = blockIdx.x * 8 + warp;
    if (row >= NPAD) return;
    if (row >= NDIM) {                 // keep pad region of next vector zero
        if (lane == 0) { g_K[j + 1][0][row] = 0.0f; g_K[j + 1][1][row] = 0.0f; }
        return;
    }
    const float4* __restrict__ Erow =
        reinterpret_cast<const float4*>(g_E) + (size_t)row * NPAD4;
    const float4* __restrict__ xq = reinterpret_cast<const float4*>(g_K[j][0]);
    const float4* __restrict__ xr = reinterpret_cast<const float4*>(g_K[j][1]);

    float4 aq = make_float4(0.f, 0.f, 0.f, 0.f);
    float4 ar = make_float4(0.f, 0.f, 0.f, 0.f);
#pragma unroll 5
    for (int it = lane; it < NPAD4; it += 32) {
        float4 e = __ldcs(Erow + it);   // streaming: no reuse of E within pass
        float4 q = __ldg(xq + it);      // x vectors are hot in L1/L2
        float4 r = __ldg(xr + it);
        aq.x = fmaf(e.x, q.x, aq.x); aq.y = fmaf(e.y, q.y, aq.y);
        aq.z = fmaf(e.z, q.z, aq.z); aq.w = fmaf(e.w, q.w, aq.w);
        ar.x = fmaf(e.x, r.x, ar.x); ar.y = fmaf(e.y, r.y, ar.y);
        ar.z = fmaf(e.z, r.z, ar.z); ar.w = fmaf(e.w, r.w, ar.w);
    }
    float sq = (aq.x + aq.y) + (aq.z + aq.w);
    float sr = (ar.x + ar.y) + (ar.z + ar.w);
#pragma unroll
    for (int o = 16; o > 0; o >>= 1) {
        sq += __shfl_xor_sync(0xffffffffu, sq, o);
        sr += __shfl_xor_sync(0xffffffffu, sr, o);
    }
    if (lane == 0) { g_K[j + 1][0][row] = sq; g_K[j + 1][1][row] = sr; }
}

// ---------------------------------------------------------------------------
// Scaled binomials g_j(k) = C(k,j) * 0.01^j via the Pascal recurrence, double prec.
__global__ void coeff_kernel(const float* __restrict__ xs) {
    __shared__ float  xsh[NB * NT];
    __shared__ double g[NV];
    __shared__ double c[NB][NV];
    int tid = threadIdx.x;
    for (int i = tid; i < NB * NT; i += 256) xsh[i] = xs[i];   // xs (8,1,256,1) -> [b*256+t]
    if (tid < NV) g[tid] = (tid == 0) ? 1.0 : 0.0;
    if (tid < NB * NV) c[tid / NV][tid % NV] = 0.0;
    __syncthreads();
    for (int k = 0; k < NT; ++k) {
        // accumulate with g = g(k)
        if (tid < NB * NV) {
            int b = tid / NV, j = tid % NV;
            c[b][j] += (double)xsh[b * NT + (NT - 1 - k)] * g[j];
        }
        double gj = 0.0, gp = 0.0;
        if (tid < NV) { gj = g[tid]; gp = (tid > 0) ? g[tid - 1] : 0.0; }
        __syncthreads();
        if (tid < NV) g[tid] = gj + 0.01 * gp;   // g(k+1)
        __syncthreads();
    }
    if (tid < NV) g_d[tid] = g[tid];             // g(256) = C(256,j)*0.01^j
    if (tid < NB * NV) g_c[tid / NV][tid % NV] = c[tid / NV][tid % NV];
}

// ---------------------------------------------------------------------------
__global__ void combine_kernel() {
    __shared__ float dsh[NV];
    __shared__ float csh[NB][NV];
    int tid = threadIdx.x;
    if (tid < NV) dsh[tid] = (float)g_d[tid];
    if (tid < NB * NV) csh[tid / NV][tid % NV] = (float)g_c[tid / NV][tid % NV];
    __syncthreads();
    int i = blockIdx.x * blockDim.x + tid;
    if (i >= NDIM) return;
    float base = 0.0f;
    float acc[NB];
#pragma unroll
    for (int b = 0; b < NB; ++b) acc[b] = 0.0f;
#pragma unroll
    for (int j = 0; j < NV; ++j) {
        float kq = g_K[j][0][i];
        float kr = g_K[j][1][i];
        base = fmaf(dsh[j], kr, base);
#pragma unroll
        for (int b = 0; b < NB; ++b) acc[b] = fmaf(csh[b][j], kq, acc[b]);
    }
#pragma unroll
    for (int b = 0; b < NB; ++b) g_th[b][i] = base + acc[b];
}

// ---------------------------------------------------------------------------
// MLP 1 -> 64 -> 64 -> 64 -> 6, relu between. Thread per time point.
__global__ void __launch_bounds__(64) mlp_kernel(const float* __restrict__ ts,
                                                 float* __restrict__ out) {
    int b = blockIdx.x;
    __shared__ float th[NDIM];
    for (int i = threadIdx.x; i < NDIM; i += 64) th[i] = g_th[b][i];
    __syncthreads();
    int t = blockIdx.y * 64 + threadIdx.x;
    float tin = ts[b * NT + t];
    float h1[64], h2[64];
#pragma unroll
    for (int j = 0; j < 64; ++j)
        h1[j] = fmaxf(fmaf(th[j], tin, th[64 + j]), 0.0f);
#pragma unroll
    for (int o = 0; o < 64; ++o) {
        float s = th[4224 + o];
#pragma unroll
        for (int d = 0; d < 64; ++d) s = fmaf(th[128 + o * 64 + d], h1[d], s);
        h2[o] = fmaxf(s, 0.0f);
    }
#pragma unroll
    for (int o = 0; o < 64; ++o) {
        float s = th[8384 + o];
#pragma unroll
        for (int d = 0; d < 64; ++d) s = fmaf(th[4288 + o * 64 + d], h2[d], s);
        h1[o] = fmaxf(s, 0.0f);
    }
#pragma unroll
    for (int o = 0; o < 6; ++o) {
        float s = th[8832 + o];
#pragma unroll
        for (int d = 0; d < 64; ++d) s = fmaf(th[8448 + o * 64 + d], h1[d], s);
        out[((size_t)b * NT + t) * 6 + o] = s;
    }
}

// ---------------------------------------------------------------------------
extern "C" void kernel_launch(void* const* d_in, const int* in_sizes, int n_in,
                              void* d_out, int out_size) {
    const float* xs    = (const float*)d_in[0];  // (8,1,256,1)
    const float* ts    = (const float*)d_in[1];  // (8,256)
    const float* theta = (const float*)d_in[2];  // (8838,)
    const float* A     = (const float*)d_in[3];  // (8838,8838)
    const float* Bv    = (const float*)d_in[4];  // (8838,1)
    float* out = (float*)d_out;                  // (8,256,6)

    build_E_kernel<<<4736, 256>>>(A);
    init_K_kernel<<<(NPAD + 255) / 256, 256>>>(theta, Bv);
    coeff_kernel<<<1, 256>>>(xs);
    for (int j = 0; j < JMAX; ++j)
        krylov_kernel<<<NPAD / 8, 256>>>(j);
    combine_kernel<<<(NDIM + 255) / 256, 256>>>();
    mlp_kernel<<<dim3(NB, NT / 64), 64>>>(ts, out);
}

// round 11
// speedup vs baseline: 1.4997x; 1.4997x over previous
#include <cuda_runtime.h>

// Ses2Seq: th <- th A^T + x B^T scanned 256 steps, then per-batch MLP eval.
// Binomial expansion A = I + E, truncated at J=14:
//   th_final[b] = sum_j d_j * (Etil^j theta) + sum_j c_{b,j} * (Etil^j B)
// Etil = 100*(A - I) applied implicitly: krylov reads A directly, subtracts
// the diagonal 1.0 at load (exact), scales by 100 at the write.
// d_j = C(256,j)*0.01^j,  c_{b,j} = 0.01^j * sum_k x[b,255-k]*C(k,j).

#define NDIM   8838
#define N2     4419      // NDIM / 2 (float2 count per row; rows are 8B aligned)
#define JMAX   14
#define NV     15        // j = 0..14
#define NB     8
#define NT     256
#define KWARPS 16        // warps (rows) per krylov block
#define KTHREADS (KWARPS * 32)

__device__ float  g_K[NV][2][NDIM];           // [j][0]=Etil^j B, [j][1]=Etil^j theta
__device__ double g_c[NB][NV];
__device__ double g_d[NV];
__device__ float  g_th[NB][NDIM];

// ---------------------------------------------------------------------------
__global__ void init_K_kernel(const float* __restrict__ theta,
                              const float* __restrict__ Bv) {
    int i = blockIdx.x * blockDim.x + threadIdx.x;
    if (i < NDIM) {
        g_K[0][0][i] = Bv[i];
        g_K[0][1][i] = theta[i];
    }
}

// ---------------------------------------------------------------------------
// One warp per row. Both x-vectors staged in shared memory (block-wide reuse)
// so the L1tex/LSU path carries only the streaming A reads.
// y = 100 * ((A - I) x): diagonal fixed at load, *100 at the write.
__global__ void __launch_bounds__(KTHREADS, 2)
krylov_kernel(const float* __restrict__ A, int j) {
    extern __shared__ float sh[];          // [0,NDIM) = q, [NDIM,2*NDIM) = r
    float* shq = sh;
    float* shr = sh + NDIM;
    for (int i = threadIdx.x; i < NDIM; i += KTHREADS) {
        shq[i] = g_K[j][0][i];
        shr[i] = g_K[j][1][i];
    }
    __syncthreads();

    int warp = threadIdx.x >> 5;
    int lane = threadIdx.x & 31;
    int row  = blockIdx.x * KWARPS + warp;
    if (row >= NDIM) return;

    const float2* __restrict__ Arow =
        reinterpret_cast<const float2*>(A + (size_t)row * NDIM);
    const float2* __restrict__ q2 = reinterpret_cast<const float2*>(shq);
    const float2* __restrict__ r2 = reinterpret_cast<const float2*>(shr);

    const int diag2 = row >> 1;            // float2 index holding the diagonal
    const int diagc = row & 1;             // component within it

    float2 accq = make_float2(0.f, 0.f);
    float2 accr = make_float2(0.f, 0.f);
#pragma unroll 4
    for (int it = lane; it < N2; it += 32) {
        float2 e = __ldcs(Arow + it);      // streaming A
        if (it == diag2) {                 // subtract I exactly, pre-accumulate
            if (diagc) e.y -= 1.0f; else e.x -= 1.0f;
        }
        float2 q = q2[it];
        float2 r = r2[it];
        accq.x = fmaf(e.x, q.x, accq.x); accq.y = fmaf(e.y, q.y, accq.y);
        accr.x = fmaf(e.x, r.x, accr.x); accr.y = fmaf(e.y, r.y, accr.y);
    }
    float sq = accq.x + accq.y;
    float sr = accr.x + accr.y;
#pragma unroll
    for (int o = 16; o > 0; o >>= 1) {
        sq += __shfl_xor_sync(0xffffffffu, sq, o);
        sr += __shfl_xor_sync(0xffffffffu, sr, o);
    }
    if (lane == 0) {
        g_K[j + 1][0][row] = 100.0f * sq;
        g_K[j + 1][1][row] = 100.0f * sr;
    }
}

// ---------------------------------------------------------------------------
// Scaled binomials g_j(k) = C(k,j) * 0.01^j via Pascal recurrence (double).
__global__ void coeff_kernel(const float* __restrict__ xs) {
    __shared__ float  xsh[NB * NT];
    __shared__ double g[NV];
    __shared__ double c[NB][NV];
    int tid = threadIdx.x;
    for (int i = tid; i < NB * NT; i += 256) xsh[i] = xs[i];  // xs (8,1,256,1)
    if (tid < NV) g[tid] = (tid == 0) ? 1.0 : 0.0;
    if (tid < NB * NV) c[tid / NV][tid % NV] = 0.0;
    __syncthreads();
    for (int k = 0; k < NT; ++k) {
        if (tid < NB * NV) {
            int b = tid / NV, jj = tid % NV;
            c[b][jj] += (double)xsh[b * NT + (NT - 1 - k)] * g[jj];
        }
        double gj = 0.0, gp = 0.0;
        if (tid < NV) { gj = g[tid]; gp = (tid > 0) ? g[tid - 1] : 0.0; }
        __syncthreads();
        if (tid < NV) g[tid] = gj + 0.01 * gp;   // g(k+1)
        __syncthreads();
    }
    if (tid < NV) g_d[tid] = g[tid];             // C(256,j)*0.01^j
    if (tid < NB * NV) g_c[tid / NV][tid % NV] = c[tid / NV][tid % NV];
}

// ---------------------------------------------------------------------------
__global__ void combine_kernel() {
    __shared__ float dsh[NV];
    __shared__ float csh[NB][NV];
    int tid = threadIdx.x;
    if (tid < NV) dsh[tid] = (float)g_d[tid];
    if (tid < NB * NV) csh[tid / NV][tid % NV] = (float)g_c[tid / NV][tid % NV];
    __syncthreads();
    int i = blockIdx.x * blockDim.x + tid;
    if (i >= NDIM) return;
    float base = 0.0f;
    float acc[NB];
#pragma unroll
    for (int b = 0; b < NB; ++b) acc[b] = 0.0f;
#pragma unroll
    for (int jj = 0; jj < NV; ++jj) {
        float kq = g_K[jj][0][i];
        float kr = g_K[jj][1][i];
        base = fmaf(dsh[jj], kr, base);
#pragma unroll
        for (int b = 0; b < NB; ++b) acc[b] = fmaf(csh[b][jj], kq, acc[b]);
    }
#pragma unroll
    for (int b = 0; b < NB; ++b) g_th[b][i] = base + acc[b];
}

// ---------------------------------------------------------------------------
// MLP 1 -> 64 -> 64 -> 64 -> 6, relu between. Thread per time point.
__global__ void __launch_bounds__(64) mlp_kernel(const float* __restrict__ ts,
                                                 float* __restrict__ out) {
    int b = blockIdx.x;
    __shared__ float th[NDIM];
    for (int i = threadIdx.x; i < NDIM; i += 64) th[i] = g_th[b][i];
    __syncthreads();
    int t = blockIdx.y * 64 + threadIdx.x;
    float tin = ts[b * NT + t];
    float h1[64], h2[64];
#pragma unroll
    for (int jj = 0; jj < 64; ++jj)
        h1[jj] = fmaxf(fmaf(th[jj], tin, th[64 + jj]), 0.0f);
#pragma unroll
    for (int o = 0; o < 64; ++o) {
        float s = th[4224 + o];
#pragma unroll
        for (int d = 0; d < 64; ++d) s = fmaf(th[128 + o * 64 + d], h1[d], s);
        h2[o] = fmaxf(s, 0.0f);
    }
#pragma unroll
    for (int o = 0; o < 64; ++o) {
        float s = th[8384 + o];
#pragma unroll
        for (int d = 0; d < 64; ++d) s = fmaf(th[4288 + o * 64 + d], h2[d], s);
        h1[o] = fmaxf(s, 0.0f);
    }
#pragma unroll
    for (int o = 0; o < 6; ++o) {
        float s = th[8832 + o];
#pragma unroll
        for (int d = 0; d < 64; ++d) s = fmaf(th[8448 + o * 64 + d], h1[d], s);
        out[((size_t)b * NT + t) * 6 + o] = s;
    }
}

// ---------------------------------------------------------------------------
extern "C" void kernel_launch(void* const* d_in, const int* in_sizes, int n_in,
                              void* d_out, int out_size) {
    const float* xs    = (const float*)d_in[0];  // (8,1,256,1)
    const float* ts    = (const float*)d_in[1];  // (8,256)
    const float* theta = (const float*)d_in[2];  // (8838,)
    const float* A     = (const float*)d_in[3];  // (8838,8838)
    const float* Bv    = (const float*)d_in[4];  // (8838,1)
    float* out = (float*)d_out;                  // (8,256,6)

    static int smem_set = 0;
    const int smem_bytes = 2 * NDIM * (int)sizeof(float);  // 70704 B
    if (!smem_set) {
        cudaFuncSetAttribute(krylov_kernel,
                             cudaFuncAttributeMaxDynamicSharedMemorySize,
                             smem_bytes);
        smem_set = 1;
    }

    init_K_kernel<<<(NDIM + 255) / 256, 256>>>(theta, Bv);
    coeff_kernel<<<1, 256>>>(xs);
    const int kblocks = (NDIM + KWARPS - 1) / KWARPS;   // 553
    for (int j = 0; j < JMAX; ++j)
        krylov_kernel<<<kblocks, KTHREADS, smem_bytes>>>(A, j);
    combine_kernel<<<(NDIM + 255) / 256, 256>>>();
    mlp_kernel<<<dim3(NB, NT / 64), 64>>>(ts, out);
}